// round 13
// baseline (speedup 1.0000x reference)
#include <cuda_runtime.h>
#include <cuda_bf16.h>
#include <math.h>

// ---------------- Problem constants ----------------
#define BB   32
#define TT   1024
#define EE   256
#define HDD  256          // hidden per direction
#define G4   1024         // 4*HD
#define KK   48
#define NEGV (-10000.0f)

// ---------------- Device scratch (static; no allocs allowed) ----------------
__device__ float d_G[2ull * TT * G4 * BB];       // [dir][t][gate_row][b]
__device__ float d_hs[2ull * TT * HDD * BB];     // [dir][t][unit][b]
__device__ float d_feats[(size_t)BB * TT * KK];  // [b][t][k]
__device__ int   d_bar[64];                      // spin barrier counters (dir*32)

// ---------------- packed f32x2 helpers (sm_103a FFMA2) ----------------
__device__ __forceinline__ void ffma2(unsigned long long& d,
                                      unsigned long long a,
                                      unsigned long long b) {
    asm("fma.rn.f32x2 %0, %1, %2, %0;" : "+l"(d) : "l"(a), "l"(b));
}
__device__ __forceinline__ unsigned long long packf2(float lo, float hi) {
    unsigned long long v;
    asm("mov.b64 %0, {%1, %2};" : "=l"(v) : "f"(lo), "f"(hi));
    return v;
}
__device__ __forceinline__ float unpack_sum(unsigned long long v) {
    float lo, hi;
    asm("mov.b64 {%0, %1}, %2;" : "=f"(lo), "=f"(hi) : "l"(v));
    return lo + hi;
}

// =====================================================================
// Kernel 0: reset barrier counters (fresh for every graph replay)
// =====================================================================
__global__ void k_reset() {
    if (threadIdx.x < 64) d_bar[threadIdx.x] = 0;
}

// =====================================================================
// Kernel 1: fused embedding-gather + input GEMM (+ bih + bhh), FFMA2.
// M = 32768 tokens (token = t*32+b), N = 2048 (2 dirs x 1024), K = 256
// CTA tile 64x64, 256 threads, 4x4 microtile, K-chunk 16 (8 k-pairs).
// =====================================================================
__global__ void __launch_bounds__(256) k_gemm_in(
    const int*   __restrict__ sent,
    const float* __restrict__ emb,
    const float* __restrict__ Wf,  const float* __restrict__ Wb,
    const float* __restrict__ bif, const float* __restrict__ bhf,
    const float* __restrict__ bib, const float* __restrict__ bhb)
{
    __shared__ __align__(16) float aT[8 * 132];   // [kpair][token(float2)]
    __shared__ __align__(16) float wT[8 * 132];   // [kpair][row(float2)]
    __shared__ int tok[64];

    int tid = threadIdx.x;
    int mt  = blockIdx.x;            // 0..511  token tiles of 64
    int nt  = blockIdx.y;            // 0..31   row tiles of 64
    int d   = nt >> 4;
    int rbase = (nt & 15) * 64;
    const float* W = d ? Wb : Wf;

    if (tid < 64) {
        int token = mt * 64 + tid;
        int t = token >> 5, b = token & 31;
        tok[tid] = sent[b * TT + t];
    }
    __syncthreads();

    unsigned long long acc2[4][4];
#pragma unroll
    for (int i = 0; i < 4; ++i)
#pragma unroll
        for (int j = 0; j < 4; ++j) acc2[i][j] = 0ull;

    int lm = tid >> 2;            // 0..63  load row (m or n index)
    int kq = (tid & 3) * 4;       // 0,4,8,12
    int mx = tid & 15;            // compute grid 16 x 16
    int nx = tid >> 4;

    for (int kc = 0; kc < EE; kc += 16) {
        float4 av = *(const float4*)&emb[(size_t)tok[lm] * EE + kc + kq];
        float4 wv = *(const float4*)&W[(size_t)(rbase + lm) * EE + kc + kq];
        __syncthreads();
        int kp0 = kq >> 1;
        *(float2*)&aT[kp0 * 132 + lm * 2]       = make_float2(av.x, av.y);
        *(float2*)&aT[(kp0 + 1) * 132 + lm * 2] = make_float2(av.z, av.w);
        *(float2*)&wT[kp0 * 132 + lm * 2]       = make_float2(wv.x, wv.y);
        *(float2*)&wT[(kp0 + 1) * 132 + lm * 2] = make_float2(wv.z, wv.w);
        __syncthreads();
#pragma unroll
        for (int kp = 0; kp < 8; ++kp) {
            ulonglong2 av0 = *(const ulonglong2*)&aT[kp * 132 + mx * 8];
            ulonglong2 av1 = *(const ulonglong2*)&aT[kp * 132 + mx * 8 + 4];
            ulonglong2 wv0 = *(const ulonglong2*)&wT[kp * 132 + nx * 8];
            ulonglong2 wv1 = *(const ulonglong2*)&wT[kp * 132 + nx * 8 + 4];
            unsigned long long am[4] = {av0.x, av0.y, av1.x, av1.y};
            unsigned long long wn[4] = {wv0.x, wv0.y, wv1.x, wv1.y};
#pragma unroll
            for (int ni = 0; ni < 4; ++ni)
#pragma unroll
                for (int mi = 0; mi < 4; ++mi)
                    ffma2(acc2[ni][mi], wn[ni], am[mi]);
        }
    }

    const float* bi = d ? bib : bif;
    const float* bh = d ? bhb : bhf;
    int token0 = mt * 64 + mx * 4;
    int t  = token0 >> 5;
    int b0 = token0 & 31;
#pragma unroll
    for (int ni = 0; ni < 4; ++ni) {
        int r = rbase + nx * 4 + ni;
        float bias = bi[r] + bh[r];
        float4 o;
        o.x = unpack_sum(acc2[ni][0]) + bias;
        o.y = unpack_sum(acc2[ni][1]) + bias;
        o.z = unpack_sum(acc2[ni][2]) + bias;
        o.w = unpack_sum(acc2[ni][3]) + bias;
        *(float4*)&d_G[(((size_t)d * TT + t) * G4 + r) * BB + b0] = o;
    }
}

// =====================================================================
// Kernel 2: persistent bidirectional LSTM recurrence (FFMA2 mainloop)
// =====================================================================
__device__ __forceinline__ float sigf(float x) { return 1.0f / (1.0f + expf(-x)); }

__global__ void __launch_bounds__(256, 1) k_lstm(
    const float* __restrict__ Whf, const float* __restrict__ Whb)
{
    __shared__ __align__(16) float w_sm[16][256];
    __shared__ float ps[8][16][32];

    int tid  = threadIdx.x;
    int lane = tid & 31;                           // batch
    int wid  = tid >> 5;                           // k-slice / warp id
    int dir  = blockIdx.x >> 6;
    int u0   = (blockIdx.x & 63) * 4;
    const float* Wh = dir ? Whb : Whf;

    for (int idx = tid; idx < 16 * 256; idx += 256) {
        int r = idx >> 8, k = idx & 255;
        int grow = (r >> 2) * HDD + u0 + (r & 3);
        w_sm[r][k] = Wh[(size_t)grow * HDD + k];
    }
    __syncthreads();

    float c = 0.f;
    int ui = wid & 3;
    size_t gbase = (size_t)dir * TT * G4 * BB;
    size_t hbase = (size_t)dir * TT * HDD * BB;
    int* barp = &d_bar[dir * 32];

    for (int s = 0; s < TT; ++s) {
        int t = dir ? (TT - 1 - s) : s;

        float gin[4];
        if (tid < 128) {
#pragma unroll
            for (int g = 0; g < 4; ++g)
                gin[g] = d_G[gbase + ((size_t)t * G4 + g * HDD + u0 + ui) * BB + lane];
        }

        if (s > 0) {
            if (tid == 0) {
                unsigned tgt = (unsigned)(s << 6);
                unsigned v;
                do {
                    asm volatile("ld.acquire.gpu.global.u32 %0, [%1];"
                                 : "=r"(v) : "l"(barp) : "memory");
                } while (v < tgt);
            }
            __syncthreads();
        }

        unsigned long long acc2[16];
#pragma unroll
        for (int r = 0; r < 16; ++r) acc2[r] = 0ull;

        if (s > 0) {
            int tp = dir ? (t + 1) : (t - 1);
            const float* hp = &d_hs[hbase + ((size_t)tp * HDD + wid * 32) * BB + lane];
            unsigned long long h2[16];
#pragma unroll
            for (int i = 0; i < 16; ++i)
                h2[i] = packf2(hp[(size_t)(2 * i) * 32], hp[(size_t)(2 * i + 1) * 32]);
            const float* wb = &w_sm[0][0] + wid * 32;
#pragma unroll
            for (int r = 0; r < 16; ++r) {
                const ulonglong2* wr = (const ulonglong2*)(wb + r * 256);
#pragma unroll
                for (int i2 = 0; i2 < 8; ++i2) {
                    ulonglong2 w2 = wr[i2];
                    ffma2(acc2[r], w2.x, h2[2 * i2]);
                    ffma2(acc2[r], w2.y, h2[2 * i2 + 1]);
                }
            }
        }

#pragma unroll
        for (int r = 0; r < 16; ++r) ps[wid][r][lane] = unpack_sum(acc2[r]);
        __syncthreads();

        if (tid < 128) {
            float gi = gin[0], gf = gin[1], gg = gin[2], go = gin[3];
#pragma unroll
            for (int w = 0; w < 8; ++w) {
                gi += ps[w][ui][lane];
                gf += ps[w][ui + 4][lane];
                gg += ps[w][ui + 8][lane];
                go += ps[w][ui + 12][lane];
            }
            c = sigf(gf) * c + sigf(gi) * tanhf(gg);
            float h = sigf(go) * tanhf(c);
            d_hs[hbase + ((size_t)t * HDD + u0 + ui) * BB + lane] = h;
        }
        __syncthreads();
        if (tid == 0) {
            unsigned one = 1;
            asm volatile("red.release.gpu.global.add.u32 [%0], %1;"
                         :: "l"(barp), "r"(one) : "memory");
        }
    }
}

// =====================================================================
// Kernel 3: feats GEMM (transposed h tile, conflict-free)
// =====================================================================
__global__ void __launch_bounds__(256) k_feats(
    const float* __restrict__ Wout, const float* __restrict__ bout)
{
    __shared__ float hsm[128][33];
    __shared__ __align__(16) float wsm[48][128];

    int tid = threadIdx.x;
    int t   = blockIdx.x;
    int b   = tid & 31;
    int kw  = tid >> 5;

    float acc[6];
#pragma unroll
    for (int p = 0; p < 6; ++p) acc[p] = 0.f;

    for (int cck = 0; cck < 4; ++cck) {
        for (int idx = tid; idx < 128 * 32; idx += 256) {
            int i = idx >> 5, b2 = idx & 31;
            int uu = cck * 128 + i;
            int dd = uu >> 8;
            int u  = uu & 255;
            hsm[i][b2] = d_hs[(((size_t)dd * TT + t) * HDD + u) * BB + b2];
        }
        for (int idx = tid; idx < 48 * 128; idx += 256) {
            int k = idx >> 7, i = idx & 127;
            wsm[k][i] = Wout[(size_t)k * 512 + cck * 128 + i];
        }
        __syncthreads();

#pragma unroll 4
        for (int i4 = 0; i4 < 32; ++i4) {
            float h0 = hsm[i4 * 4 + 0][b];
            float h1 = hsm[i4 * 4 + 1][b];
            float h2v = hsm[i4 * 4 + 2][b];
            float h3 = hsm[i4 * 4 + 3][b];
#pragma unroll
            for (int p = 0; p < 6; ++p) {
                float4 w4 = *(const float4*)&wsm[kw + 8 * p][i4 * 4];
                acc[p] += w4.x * h0 + w4.y * h1 + w4.z * h2v + w4.w * h3;
            }
        }
        __syncthreads();
    }

#pragma unroll
    for (int p = 0; p < 6; ++p) {
        int k = kw + 8 * p;
        d_feats[((size_t)b * TT + t) * KK + k] = acc[p] + bout[k];
    }
}

// =====================================================================
// Kernel 4: Viterbi per batch. 32 CTAs x 64 threads, 6 max-chains.
// =====================================================================
#define VIT_TRP   (48 * 49 * 4)
#define VIT_BPTR  (1024 * 48)
#define VIT_FV    (2 * 48 * 4)
#define VIT_TAGS  (1024 * 4)
#define VIT_SMEM  (VIT_TRP + VIT_BPTR + VIT_FV + VIT_TAGS)

__global__ void __launch_bounds__(64) k_viterbi(
    const float* __restrict__ trans, float* __restrict__ out)
{
    extern __shared__ char sm[];
    float*         trp  = (float*)sm;
    unsigned char* bptr = (unsigned char*)(sm + VIT_TRP);
    float*         fvA  = (float*)(sm + VIT_TRP + VIT_BPTR);
    float*         fvB  = fvA + 48;
    int*           tags = (int*)(sm + VIT_TRP + VIT_BPTR + VIT_FV);
    __shared__ float redsm[64];

    int b = blockIdx.x, tid = threadIdx.x;
    const float* fb = d_feats + (size_t)b * TT * KK;

    for (int idx = tid; idx < 48 * 48; idx += 64)
        trp[(idx / 48) * 49 + (idx % 48)] = trans[idx];
    if (tid < 48) fvA[tid] = (tid == 47) ? 0.f : NEGV;
    __syncthreads();

    float* fv  = fvA;
    float* fvn = fvB;
    const float* trow = &trp[tid * 49];
    for (int t = 0; t < TT; ++t) {
        if (tid < 48) {
            float ft = fb[t * KK + tid];
            float m[6]; int a[6];
#pragma unroll
            for (int cch = 0; cch < 6; ++cch) {
                m[cch] = fv[cch] + trow[cch];
                a[cch] = cch;
            }
#pragma unroll
            for (int jj = 1; jj < 8; ++jj)
#pragma unroll
                for (int cch = 0; cch < 6; ++cch) {
                    int j = jj * 6 + cch;
                    float v = fv[j] + trow[j];
                    if (v > m[cch]) { m[cch] = v; a[cch] = j; }
                }
            float M = m[0]; int A = a[0];
#pragma unroll
            for (int cch = 1; cch < 6; ++cch)
                if (m[cch] > M || (m[cch] == M && a[cch] < A)) { M = m[cch]; A = a[cch]; }
            fvn[tid] = M + ft;
            bptr[t * 48 + tid] = (unsigned char)A;
        }
        __syncthreads();
        float* tmp = fv; fv = fvn; fvn = tmp;
    }

    if (tid == 0) {
        float m = -1e30f; int last = 0;
        for (int j = 0; j < 48; ++j)
            if (fv[j] > m) { m = fv[j]; last = j; }
        tags[TT - 1] = last;
        int cur = last;
        for (int t = TT - 2; t >= 0; --t) {
            cur = bptr[(t + 1) * 48 + cur];
            tags[t] = cur;
        }
    }
    __syncthreads();

    for (int t = tid; t < TT; t += 64)
        out[32 + b * TT + t] = (float)tags[t];

    float s = 0.f;
    for (int t = tid; t < TT - 1; t += 64)
        s += trp[tags[t] * 49 + tags[t + 1]];
    for (int t = tid; t < TT; t += 64)
        if (t >= 1) s += fb[t * KK + tags[t]];
    redsm[tid] = s;
    __syncthreads();
    if (tid == 0) {
        float tot = fb[(TT - 1) * KK + tags[0]];
        for (int i = 0; i < 64; ++i) tot += redsm[i];
        out[b] = tot;
    }
}

// =====================================================================
extern "C" void kernel_launch(void* const* d_in, const int* in_sizes, int n_in,
                              void* d_out, int out_size)
{
    const int*   sent  = (const int*)  d_in[0];
    const float* emb   = (const float*)d_in[1];
    const float* Wih_f = (const float*)d_in[2];
    const float* Whh_f = (const float*)d_in[3];
    const float* bih_f = (const float*)d_in[4];
    const float* bhh_f = (const float*)d_in[5];
    const float* Wih_b = (const float*)d_in[6];
    const float* Whh_b = (const float*)d_in[7];
    const float* bih_b = (const float*)d_in[8];
    const float* bhh_b = (const float*)d_in[9];
    const float* W_out = (const float*)d_in[10];
    const float* b_out = (const float*)d_in[11];
    const float* trans = (const float*)d_in[12];
    float* out = (float*)d_out;

    cudaFuncSetAttribute(k_viterbi, cudaFuncAttributeMaxDynamicSharedMemorySize, 65536);

    k_reset<<<1, 64>>>();

    dim3 g1(512, 32);
    k_gemm_in<<<g1, 256>>>(sent, emb, Wih_f, Wih_b, bih_f, bhh_f, bih_b, bhh_b);

    k_lstm<<<128, 256>>>(Whh_f, Whh_b);

    k_feats<<<TT, 256>>>(W_out, b_out);

    k_viterbi<<<BB, 64, VIT_SMEM>>>(trans, out);
}